// round 10
// baseline (speedup 1.0000x reference)
#include <cuda_runtime.h>

// FlowNetC correlation, specialized: B=4, C=128, H=W=96, PAD=20, K=1, MD=20, S1=1, S2=2
// out[b, iy*21+ix, y, x] = (1/128) * sum_c in1[b,c,y,x] * in2[b,c,y+dy,x+dx]
//
// R10: 4 output columns per thread (halves compute LDS vs 2-wide), cg over 8
// lanes (granules cg, cg+8 per 64-ch chunk), 2-pass chunk staging like R7/R9.
// The 84-accumulator problem is solved by j-halves with raw partial sums parked
// in `out` between chunks (same-thread global RMW), keeping live accs <= 44.

#define HW_ 9216            // 96*96 plane stride in floats
#define RS  68              // padded row stride for 64-ch chunk (floats)
#define S1F (96*RS)         // 6528
#define S2ROWS 136          // x in [-20,115] -> row = x+20
#define S2F (S2ROWS*RS)     // 9248
#define SMEM_BYTES ((S1F + S2F)*4)   // 63,104 B

__device__ __forceinline__ void stage_chunk(const float* __restrict__ in1,
                                            const float* __restrict__ in2,
                                            float* __restrict__ s1,
                                            float* __restrict__ s2,
                                            int b, int y, int y2, int cc, int tid)
{
    const float* g1 = in1 + ((size_t)(b * 128 + cc * 64) * 96 + y) * 96;
    #pragma unroll 1
    for (int i = tid; i < 96 * 16; i += 192) {
        int x = i % 96, g = i / 96;                 // g = float4 granule 0..15
        const float* p = g1 + g * 4 * HW_ + x;
        *(float4*)&s1[x * RS + g * 4] = make_float4(p[0], p[HW_], p[2*HW_], p[3*HW_]);
    }
    const float* g2 = in2 + ((size_t)(b * 128 + cc * 64) * 96 + y2) * 96;
    #pragma unroll 1
    for (int i = tid; i < 96 * 16; i += 192) {
        int x = i % 96, g = i / 96;
        const float* p = g2 + g * 4 * HW_ + x;
        *(float4*)&s2[(x + 20) * RS + g * 4] = make_float4(p[0], p[HW_], p[2*HW_], p[3*HW_]);
    }
}

// Accumulate the staged 64-ch chunk into acc[xi][jl], j = JLO+jl, for 4 output
// columns x0+2*xi. Lane owns granules cg and cg+8. bv row = x0 + 2*(JLO+u),
// u = jl + xi in [0, NJ+3).
template<int NJ>
__device__ __forceinline__ void accum4(const float* __restrict__ s1,
                                       const float* __restrict__ s2,
                                       int x0, int cg, int JLO, float (&acc)[4][NJ])
{
    #pragma unroll
    for (int k = 0; k < 2; k++) {
        const int cb = cg + 8 * k;
        const float* p1 = s1 + x0 * RS + cb * 4;
        const float4 a0 = *(const float4*)(p1);
        const float4 a1 = *(const float4*)(p1 + 2 * RS);
        const float4 a2 = *(const float4*)(p1 + 4 * RS);
        const float4 a3 = *(const float4*)(p1 + 6 * RS);
        const float* p2 = s2 + (x0 + 2 * JLO) * RS + cb * 4;
        #pragma unroll
        for (int u = 0; u < NJ + 3; u++) {
            const float4 bv = *(const float4*)(p2 + 2 * u * RS);
            if (u < NJ) {
                float v = acc[0][u];
                v = fmaf(a0.x, bv.x, v); v = fmaf(a0.y, bv.y, v);
                v = fmaf(a0.z, bv.z, v); v = fmaf(a0.w, bv.w, v);
                acc[0][u] = v;
            }
            if (u >= 1 && u - 1 < NJ) {
                float v = acc[1][u - 1];
                v = fmaf(a1.x, bv.x, v); v = fmaf(a1.y, bv.y, v);
                v = fmaf(a1.z, bv.z, v); v = fmaf(a1.w, bv.w, v);
                acc[1][u - 1] = v;
            }
            if (u >= 2 && u - 2 < NJ) {
                float v = acc[2][u - 2];
                v = fmaf(a2.x, bv.x, v); v = fmaf(a2.y, bv.y, v);
                v = fmaf(a2.z, bv.z, v); v = fmaf(a2.w, bv.w, v);
                acc[2][u - 2] = v;
            }
            if (u >= 3 && u - 3 < NJ) {
                float v = acc[3][u - 3];
                v = fmaf(a3.x, bv.x, v); v = fmaf(a3.y, bv.y, v);
                v = fmaf(a3.z, bv.z, v); v = fmaf(a3.w, bv.w, v);
                acc[3][u - 3] = v;
            }
        }
    }
}

// Butterfly-reduce across the 8 cg lanes; lane cg handles xi=cg&3, j parity cg>>2.
// FINAL=0: store raw partial. FINAL=1: add previously stored partial, scale, store.
template<int NJ, int FINAL>
__device__ __forceinline__ void reduce_store(float (&acc)[4][NJ], int JLO, int x0,
                                             int cg, float* __restrict__ out,
                                             size_t obase)
{
    #pragma unroll
    for (int xi = 0; xi < 4; xi++)
        #pragma unroll
        for (int j = 0; j < NJ; j++) {
            float v = acc[xi][j];
            v += __shfl_xor_sync(0xffffffffu, v, 1);
            v += __shfl_xor_sync(0xffffffffu, v, 2);
            v += __shfl_xor_sync(0xffffffffu, v, 4);
            acc[xi][j] = v;
        }
    const float inv  = 1.0f / 128.0f;
    const int   myxi = cg & 3;
    const int   par  = cg >> 2;
    float* o = out + obase + x0 + 2 * myxi;
    #pragma unroll
    for (int j = 0; j < NJ; j++) {
        if (((JLO + j) & 1) == par) {
            float* p = o + (size_t)(JLO + j) * HW_;
            if (FINAL)
                *p = (*p + acc[myxi][j]) * inv;
            else
                *p = acc[myxi][j];
        }
    }
}

__global__ __launch_bounds__(192, 3)
void corr_kernel(const float* __restrict__ in1, const float* __restrict__ in2,
                 float* __restrict__ out)
{
    extern __shared__ float smem[];
    float* s1 = smem;
    float* s2 = smem + S1F;

    const int tid   = threadIdx.x;
    const int y     = blockIdx.x;    // 0..95
    const int dyIdx = blockIdx.y;    // 0..20
    const int b     = blockIdx.z;    // 0..3

    const int y2 = y + (dyIdx - 10) * 2;
    const size_t obase = ((size_t)(b * 441 + dyIdx * 21) * 96 + y) * 96;

    if ((unsigned)y2 >= 96u) {
        // whole dy slab for this row is zeros
        for (int i = tid; i < 21 * 96; i += 192) {
            int j = i / 96, x = i - j * 96;
            out[obase + (size_t)j * HW_ + x] = 0.f;
        }
        return;
    }

    // zero halo rows of s2 once (x in [-20,-1] and [96,115]); never overwritten
    for (int i = tid; i < 40 * 16; i += 192) {
        int r = i % 40, g = i / 40;
        int row = (r < 20) ? r : (96 + r);        // rows 0..19, 116..135
        *(float4*)&s2[row * RS + g * 4] = make_float4(0.f, 0.f, 0.f, 0.f);
    }

    const int cg = tid & 7;                  // channel granule lane
    const int xs = tid >> 3;                 // 0..23
    const int x0 = 8 * (xs >> 1) + (xs & 1); // outputs x0+2*xi, xi=0..3, tile 0..95

    // ---- chunk 0: compute both j-halves, park raw partials in out ----
    stage_chunk(in1, in2, s1, s2, b, y, y2, 0, tid);
    __syncthreads();
    {
        float acc[4][11];
        #pragma unroll
        for (int xi = 0; xi < 4; xi++)
            #pragma unroll
            for (int j = 0; j < 11; j++) acc[xi][j] = 0.f;
        accum4<11>(s1, s2, x0, cg, 0, acc);
        reduce_store<11, 0>(acc, 0, x0, cg, out, obase);
    }
    {
        float acc[4][10];
        #pragma unroll
        for (int xi = 0; xi < 4; xi++)
            #pragma unroll
            for (int j = 0; j < 10; j++) acc[xi][j] = 0.f;
        accum4<10>(s1, s2, x0, cg, 11, acc);
        reduce_store<10, 0>(acc, 11, x0, cg, out, obase);
    }
    __syncthreads();

    // ---- chunk 1: accumulate, combine with parked partials, finalize ----
    stage_chunk(in1, in2, s1, s2, b, y, y2, 1, tid);
    __syncthreads();
    {
        float acc[4][11];
        #pragma unroll
        for (int xi = 0; xi < 4; xi++)
            #pragma unroll
            for (int j = 0; j < 11; j++) acc[xi][j] = 0.f;
        accum4<11>(s1, s2, x0, cg, 0, acc);
        reduce_store<11, 1>(acc, 0, x0, cg, out, obase);
    }
    {
        float acc[4][10];
        #pragma unroll
        for (int xi = 0; xi < 4; xi++)
            #pragma unroll
            for (int j = 0; j < 10; j++) acc[xi][j] = 0.f;
        accum4<10>(s1, s2, x0, cg, 11, acc);
        reduce_store<10, 1>(acc, 11, x0, cg, out, obase);
    }
}

extern "C" void kernel_launch(void* const* d_in, const int* in_sizes, int n_in,
                              void* d_out, int out_size)
{
    const float* in1 = (const float*)d_in[0];
    const float* in2 = (const float*)d_in[1];
    float* out = (float*)d_out;

    cudaFuncSetAttribute(corr_kernel, cudaFuncAttributeMaxDynamicSharedMemorySize, SMEM_BYTES);

    dim3 grid(96, 21, 4);   // y, dy, batch
    corr_kernel<<<grid, 192, SMEM_BYTES>>>(in1, in2, out);
}